// round 4
// baseline (speedup 1.0000x reference)
#include <cuda_runtime.h>

#define NUM_HEADS 12
#define HD 64
#define BATCH 8
#define HH 32
#define WW 32
#define S 1024          // HH*WW
#define C 768
#define BHN 96          // BATCH*NUM_HEADS

typedef unsigned long long ull;

// packed f32x2 helpers (Blackwell FFMA2 path — only reachable via PTX)
__device__ __forceinline__ void fma2(ull& acc, ull a, ull b) {
    asm("fma.rn.f32x2 %0, %1, %2, %0;" : "+l"(acc) : "l"(a), "l"(b));
}
__device__ __forceinline__ ull mul2(ull a, ull b) {
    ull d; asm("mul.rn.f32x2 %0, %1, %2;" : "=l"(d) : "l"(a), "l"(b)); return d;
}
__device__ __forceinline__ ull splat2(float x) {
    ull d; asm("mov.b64 %0, {%1, %1};" : "=l"(d) : "f"(x)); return d;
}
__device__ __forceinline__ float lo32(ull x) { return __uint_as_float((unsigned)x); }
__device__ __forceinline__ float hi32(ull x) { return __uint_as_float((unsigned)(x >> 32)); }
__device__ __forceinline__ ull lds64(const float* p) { return *(const ull*)p; }

// ---------------- scratch (no allocations allowed) ----------------
__device__ __align__(16) float g_q[(size_t)BHN * S * HD];
__device__ __align__(16) float g_k[(size_t)BHN * S * HD];
__device__ __align__(16) float g_v[(size_t)BHN * S * HD];
__device__ __align__(16) float g_relh[(size_t)BHN * S * HH];
__device__ __align__(16) float g_relw[(size_t)BHN * S * WW];
__device__ __align__(16) float g_att[(size_t)BATCH * S * C];

// ---------------- 128x128x8 fp32 GEMM, f32x2 packed FMA ----------------
// Thread microtile: rows m = ty+16i (i<8), cols n = 2*tx+32*jp+{0,1} (jp<4).
// A stored duplicated (splat via LDS.64), B pairs natural.
// MODE 0: C = A @ B + bias, scatter into g_q/g_k/g_v
// MODE 1: C = g_att @ B + bias -> Cout
template <int MODE>
__global__ __launch_bounds__(256) void gemm_k(const float* __restrict__ A,
                                              const float* __restrict__ B,
                                              const float* __restrict__ bias,
                                              float* __restrict__ Cout,
                                              int M, int N, int K)
{
    __shared__ __align__(16) float As2[8][258];   // duplicated: col 2r, 2r+1 both = a[r]
    __shared__ __align__(16) float Bs[8][132];

    const float* Ap = (MODE == 1) ? (const float*)g_att : A;

    const int tid = threadIdx.x;
    const int tx = tid & 15, ty = tid >> 4;
    const int bm = blockIdx.y * 128, bn = blockIdx.x * 128;

    ull acc[8][4];
#pragma unroll
    for (int i = 0; i < 8; i++)
#pragma unroll
        for (int j = 0; j < 4; j++) acc[i][j] = 0ull;

    const int arow = tid >> 1, acol = (tid & 1) * 4;
    const int brow = tid >> 5, bcol = (tid & 31) * 4;

    for (int k0 = 0; k0 < K; k0 += 8) {
        float4 av = *(const float4*)(Ap + (size_t)(bm + arow) * K + k0 + acol);
        float4 bv = *(const float4*)(B + (size_t)(k0 + brow) * N + bn + bcol);
        As2[acol + 0][2 * arow] = av.x; As2[acol + 0][2 * arow + 1] = av.x;
        As2[acol + 1][2 * arow] = av.y; As2[acol + 1][2 * arow + 1] = av.y;
        As2[acol + 2][2 * arow] = av.z; As2[acol + 2][2 * arow + 1] = av.z;
        As2[acol + 3][2 * arow] = av.w; As2[acol + 3][2 * arow + 1] = av.w;
        *(float4*)&Bs[brow][bcol] = bv;
        __syncthreads();
#pragma unroll
        for (int kk = 0; kk < 8; kk++) {
            ull a2[8], b2[4];
#pragma unroll
            for (int i = 0; i < 8; i++) a2[i] = lds64(&As2[kk][2 * (ty + 16 * i)]);
#pragma unroll
            for (int j = 0; j < 4; j++) b2[j] = lds64(&Bs[kk][2 * tx + 32 * j]);
#pragma unroll
            for (int i = 0; i < 8; i++)
#pragma unroll
                for (int j = 0; j < 4; j++)
                    fma2(acc[i][j], a2[i], b2[j]);
        }
        __syncthreads();
    }

#pragma unroll
    for (int i = 0; i < 8; i++) {
        const int m = bm + ty + 16 * i;
        const int b = m >> 10, s = m & 1023;
#pragma unroll
        for (int j = 0; j < 4; j++) {
            const int n0 = bn + 2 * tx + 32 * j;
            const float v0 = lo32(acc[i][j]) + bias[n0];
            const float v1 = hi32(acc[i][j]) + bias[n0 + 1];
            if (MODE == 0) {
#pragma unroll
                for (int h = 0; h < 2; h++) {
                    const int n = n0 + h;
                    const float v = h ? v1 : v0;
                    const int t   = n / C;
                    const int rem = n - t * C;
                    const int hh  = rem >> 6;
                    const int d   = rem & 63;
                    float* dst = (t == 0) ? g_q : (t == 1) ? g_k : g_v;
                    dst[((size_t)(b * NUM_HEADS + hh) * S + s) * HD + d] = v;
                }
            } else {
                float2 st; st.x = v0; st.y = v1;
                *(float2*)(Cout + (size_t)m * N + n0) = st;
            }
        }
    }
}

// ---------------- relative-position bias tables ----------------
__global__ __launch_bounds__(128) void rel_kernel(const float* __restrict__ table, int mode)
{
    __shared__ float tab[63][65];
    __shared__ float qs[32][65];
    const int bh = blockIdx.y;
    const int h  = blockIdx.x;
    const int tid = threadIdx.x;

    for (int idx = tid; idx < 63 * 64; idx += 128)
        tab[idx >> 6][idx & 63] = table[idx];
    const float* qbase = g_q + ((size_t)bh * S + h * 32) * HD;
    for (int idx = tid; idx < 32 * 64; idx += 128)
        qs[idx >> 6][idx & 63] = qbase[idx];
    __syncthreads();

    float* out = (mode == 0) ? g_relh : g_relw;
    float* obase = out + ((size_t)bh * 32 + h) * 32 * 32;

    for (int o = tid; o < 1024; o += 128) {
        const int w = o >> 5, j = o & 31;
        const int row = (mode == 0) ? (h - j + 31) : (w - j + 31);
        const float* qr = qs[w];
        const float* tr = tab[row];
        float a0 = 0.f, a1 = 0.f, a2 = 0.f, a3 = 0.f;
#pragma unroll
        for (int d = 0; d < 64; d += 4) {
            a0 = fmaf(qr[d + 0], tr[d + 0], a0);
            a1 = fmaf(qr[d + 1], tr[d + 1], a1);
            a2 = fmaf(qr[d + 2], tr[d + 2], a2);
            a3 = fmaf(qr[d + 3], tr[d + 3], a3);
        }
        obase[o] = (a0 + a1) + (a2 + a3);
    }
}

// ---------------- fused attention, f32x2 packed ----------------
// Block: 128 query rows, 128 threads, 32-key tiles.
// QK: 8q x 4k microtile, PACKED ALONG hd (reduction) — no splats, collapse per tile.
//     rows  = qty + 16*i   (conflict-free q loads)
//     keys  = qtx + 8*j    (conflict-free k loads)
// PV: 8q x 8d microtile, PACKED ALONG d; prob splat via duplicated sc2 storage.
//     d     = 2*qtx + 16*jp + {0,1}  (conflict-free v loads)
struct AttSmem {
    float q  [128][66];  // query rows, pre-scaled (pad 66: LDS.64 conflict-free)
    float sc [128][33];  // raw scores (pad 33: per-row softmax reads)
    float sc2[128][66];  // probabilities DUPLICATED: col 2k,2k+1 both = p[k]
    float kv [32][66];   // K tile then V tile
    float rws[128][33];  // rel_w bias rows
    float corr[128];
    float invl[128];
};

__global__ __launch_bounds__(128) void attn_kernel()
{
    extern __shared__ char smem_raw[];
    AttSmem& sm = *reinterpret_cast<AttSmem*>(smem_raw);

    const int bh  = blockIdx.y;
    const int s0  = blockIdx.x * 128;
    const int tid = threadIdx.x;
    const int qty = tid >> 3;    // 0..15
    const int qtx = tid & 7;     // 0..7
    const float scale = 0.125f;

    // stage q (scaled), scalar stores (pad 66)
    {
        const float4* qp = (const float4*)(g_q + ((size_t)bh * S + s0) * HD);
#pragma unroll
        for (int u = 0; u < 16; u++) {
            const int idx4 = tid + 128 * u;
            float4 t = qp[idx4];
            const int r = idx4 >> 4, c = (idx4 & 15) * 4;
            sm.q[r][c + 0] = t.x * scale;
            sm.q[r][c + 1] = t.y * scale;
            sm.q[r][c + 2] = t.z * scale;
            sm.q[r][c + 3] = t.w * scale;
        }
    }
    {
        const float* rp = g_relw + ((size_t)bh * S + s0) * 32;
        for (int idx = tid; idx < 128 * 32; idx += 128)
            sm.rws[idx >> 5][idx & 31] = rp[idx];
    }

    ull o2[8][4];                 // persistent output, packed along d
#pragma unroll
    for (int i = 0; i < 8; i++)
#pragma unroll
        for (int j = 0; j < 4; j++) o2[i][j] = 0ull;

    float mrun = -1e30f, lrun = 0.f;

    for (int kt0 = 0; kt0 < S; kt0 += 32) {
        __syncthreads();          // kv free

        // ---- load K tile (row-major, pad 66) ----
        {
            const float4* kp = (const float4*)(g_k + ((size_t)bh * S + kt0) * HD);
            float4 kreg[4];
#pragma unroll
            for (int u = 0; u < 4; u++) kreg[u] = kp[tid + 128 * u];
#pragma unroll
            for (int u = 0; u < 4; u++) {
                const int idx4 = tid + 128 * u;
                const int r = idx4 >> 4, c = (idx4 & 15) * 4;
                sm.kv[r][c + 0] = kreg[u].x;
                sm.kv[r][c + 1] = kreg[u].y;
                sm.kv[r][c + 2] = kreg[u].z;
                sm.kv[r][c + 3] = kreg[u].w;
            }
        }
        __syncthreads();

        // ---- QK: packed along hd, 8q x 4k ----
        {
            ull acc[8][4];
#pragma unroll
            for (int i = 0; i < 8; i++)
#pragma unroll
                for (int j = 0; j < 4; j++) acc[i][j] = 0ull;

#pragma unroll 8
            for (int kkp = 0; kkp < 32; kkp++) {
                ull a2[8], b2[4];
#pragma unroll
                for (int i = 0; i < 8; i++) a2[i] = lds64(&sm.q[qty + 16 * i][2 * kkp]);
#pragma unroll
                for (int j = 0; j < 4; j++) b2[j] = lds64(&sm.kv[qtx + 8 * j][2 * kkp]);
#pragma unroll
                for (int i = 0; i < 8; i++)
#pragma unroll
                    for (int j = 0; j < 4; j++)
                        fma2(acc[i][j], a2[i], b2[j]);
            }
#pragma unroll
            for (int i = 0; i < 8; i++)
#pragma unroll
                for (int j = 0; j < 4; j++)
                    sm.sc[qty + 16 * i][qtx + 8 * j] = lo32(acc[i][j]) + hi32(acc[i][j]);
        }
        __syncthreads();

        // ---- softmax (thread <-> query row) + V prefetch/stage ----
        {
            const float4* vp = (const float4*)(g_v + ((size_t)bh * S + kt0) * HD);
            float4 vreg[4];
#pragma unroll
            for (int u = 0; u < 4; u++) vreg[u] = vp[tid + 128 * u];

            const float rhb = g_relh[((size_t)bh * S + s0 + tid) * 32 + (kt0 >> 5)];
            float s[32];
            float mt = -1e30f;
#pragma unroll
            for (int j = 0; j < 32; j++) {
                s[j] = sm.sc[tid][j] + sm.rws[tid][j] + rhb;
                mt = fmaxf(mt, s[j]);
            }
            const float mnew = fmaxf(mrun, mt);
            const float cf = __expf(mrun - mnew);
            lrun *= cf;
#pragma unroll
            for (int j = 0; j < 32; j++) {
                const float p = __expf(s[j] - mnew);
                lrun += p;
                *(ull*)&sm.sc2[tid][2 * j] = splat2(p);   // duplicated store
            }
            mrun = mnew;
            sm.corr[tid] = cf;
            if (kt0 == S - 32) sm.invl[tid] = 1.f / lrun;

            // stage V (same buffer as K)
#pragma unroll
            for (int u = 0; u < 4; u++) {
                const int idx4 = tid + 128 * u;
                const int r = idx4 >> 4, c = (idx4 & 15) * 4;
                sm.kv[r][c + 0] = vreg[u].x;
                sm.kv[r][c + 1] = vreg[u].y;
                sm.kv[r][c + 2] = vreg[u].z;
                sm.kv[r][c + 3] = vreg[u].w;
            }
        }
        __syncthreads();

        // ---- PV: packed along d, prob splat via LDS.64 from sc2 ----
        {
            ull c2[8];
#pragma unroll
            for (int i = 0; i < 8; i++) c2[i] = splat2(sm.corr[qty + 16 * i]);
#pragma unroll
            for (int i = 0; i < 8; i++)
#pragma unroll
                for (int j = 0; j < 4; j++) o2[i][j] = mul2(o2[i][j], c2[i]);

#pragma unroll 4
            for (int key = 0; key < 32; key++) {
                ull v2[4];
#pragma unroll
                for (int jp = 0; jp < 4; jp++)
                    v2[jp] = lds64(&sm.kv[key][2 * qtx + 16 * jp]);
#pragma unroll
                for (int i = 0; i < 8; i++) {
                    const ull p2 = lds64(&sm.sc2[qty + 16 * i][2 * key]);
#pragma unroll
                    for (int jp = 0; jp < 4; jp++)
                        fma2(o2[i][jp], p2, v2[jp]);
                }
            }
        }
    }

    // ---- epilogue: normalize + write (B, s, head*64+d) as float2 ----
    {
        const int b = bh / NUM_HEADS, head = bh % NUM_HEADS;
#pragma unroll
        for (int i = 0; i < 8; i++) {
            const int row = qty + 16 * i;
            const ull inv2 = splat2(sm.invl[row]);
            float* dst = g_att + ((size_t)(b * S + s0 + row)) * C + head * HD;
#pragma unroll
            for (int jp = 0; jp < 4; jp++) {
                const ull r = mul2(o2[i][jp], inv2);
                *(ull*)(dst + 2 * qtx + 16 * jp) = r;
            }
        }
    }
}

// ---------------- launch ----------------
extern "C" void kernel_launch(void* const* d_in, const int* in_sizes, int n_in,
                              void* d_out, int out_size)
{
    const float* x     = (const float*)d_in[0];
    const float* wqkv  = (const float*)d_in[1];
    const float* bqkv  = (const float*)d_in[2];
    const float* rph   = (const float*)d_in[3];
    const float* rpw   = (const float*)d_in[4];
    const float* wproj = (const float*)d_in[5];
    const float* bproj = (const float*)d_in[6];
    float* out = (float*)d_out;

    // 1) QKV GEMM -> g_q/g_k/g_v  (M=8192, N=2304, K=768)
    dim3 g1(2304 / 128, 8192 / 128);
    gemm_k<0><<<g1, 256>>>(x, wqkv, bqkv, nullptr, BATCH * S, 3 * C, C);

    // 2) relative-position bias tables
    rel_kernel<<<dim3(32, BHN), 128>>>(rph, 0);
    rel_kernel<<<dim3(32, BHN), 128>>>(rpw, 1);

    // 3) fused attention -> g_att
    const size_t attn_smem = sizeof(AttSmem);
    cudaFuncSetAttribute(attn_kernel, cudaFuncAttributeMaxDynamicSharedMemorySize,
                         (int)attn_smem);
    attn_kernel<<<dim3(S / 128, BHN), 128, attn_smem>>>();

    // 4) output projection -> d_out  (M=8192, N=768, K=768)
    dim3 g2(768 / 128, 8192 / 128);
    gemm_k<1><<<g2, 256>>>(nullptr, wproj, bproj, out, BATCH * S, C, C);
}